// round 2
// baseline (speedup 1.0000x reference)
#include <cuda_runtime.h>
#include <cuda_bf16.h>

#define NN 100000
#define EE 1600000
#define RRR 8
#define KDIM 192            // bf16 split K: [hi | lo | hi]
#define ASTRIDE 200         // smem row stride in bf16 (pad for bank-conflict-free frags)
#define SMEM_BYTES (128*ASTRIDE*2 + 2*64*ASTRIDE*2)   // A tile + double-buffered B chunk

// ---------------- device scratch (no allocs allowed) ----------------
__device__ __align__(16) float g_y[(size_t)NN * 512];     // per-(node,relation) transformed features
__device__ __align__(16) float g_h[(size_t)NN * 64];      // layer-1 output
__device__ __align__(16) float g_cnt[NN * RRR];           // counts -> reciprocal in place
__device__ __align__(16) int   g_sa[EE];                  // src*8 + et
__device__ __align__(16) int   g_sb[EE];                  // dst*8 + et
__device__ __align__(16) float g_acc[128];                // BN sum / sumsq
__device__ __align__(16) float g_scale[64];
__device__ __align__(16) float g_shift[64];
__device__ __align__(16) __nv_bfloat16 g_wp1[576 * KDIM]; // packed [j=r*64+o][k] bf16 weights (r==8 -> root)
__device__ __align__(16) __nv_bfloat16 g_wp2[576 * KDIM];

// ---------------- small kernels ----------------
__global__ void zero_kernel(float* cnt, float* acc) {
    int i = blockIdx.x * 256 + threadIdx.x;
    if (i < NN * RRR) cnt[i] = 0.f;
    if (i < 128) acc[i] = 0.f;
}

// NOTE: edge_index / edge_type are int32 (JAX default x64-disabled).
__global__ void prep_edges(const int* __restrict__ ei,
                           const int* __restrict__ et,
                           int* __restrict__ sa, int* __restrict__ sb,
                           float* __restrict__ cnt) {
    int e = blockIdx.x * 256 + threadIdx.x;
    if (e >= EE) return;
    int s = ei[e];
    int d = ei[EE + e];
    int r = et[e];
    sa[e] = s * RRR + r;
    int b = d * RRR + r;
    sb[e] = b;
    atomicAdd(cnt + b, 1.0f);
}

__global__ void inv_kernel(float* cnt) {
    int i = blockIdx.x * 256 + threadIdx.x;
    if (i < NN * RRR) cnt[i] = 1.0f / fmaxf(cnt[i], 1.0f);
}

// pack W[r,d,o] (+root as r==8) into bf16 [j=576][k=192]; k<64: hi(d=k), k<128: hi(d=k-64), else lo(d=k-128)
__global__ void prep_w(const float* __restrict__ w, const float* __restrict__ root,
                       __nv_bfloat16* __restrict__ wp) {
    int i = blockIdx.x * 256 + threadIdx.x;
    if (i >= 576 * KDIM) return;
    int j = i / KDIM, k = i % KDIM;
    int r = j >> 6, o = j & 63;
    int d = (k < 64) ? k : (k < 128 ? k - 64 : k - 128);
    float v = (r < RRR) ? w[((size_t)r * 64 + d) * 64 + o] : root[(size_t)d * 64 + o];
    __nv_bfloat16 hi = __float2bfloat16(v);
    wp[i] = (k < 128) ? hi : __float2bfloat16(v - __bfloat162float(hi));
}

// ---------------- GEMM: X[N,64] (fp32) -> Y[N,512] + OUT[N,64] (root+bias) ----------------
__device__ __forceinline__ void cp16(void* dst, const void* src) {
    unsigned s = (unsigned)__cvta_generic_to_shared(dst);
    asm volatile("cp.async.cg.shared.global [%0], [%1], 16;" :: "r"(s), "l"(src));
}

__device__ __forceinline__ void issue_b_chunk(__nv_bfloat16* bbuf,
                                              const __nv_bfloat16* wp, int nc, int tid) {
    const __nv_bfloat16* src0 = wp + (size_t)nc * 64 * KDIM;
#pragma unroll
    for (int i = 0; i < 6; i++) {
        int t = tid + i * 256;          // t < 1536
        int j = t / 24, seg = t % 24;   // 24 x 16B per 192-bf16 row
        cp16(bbuf + j * ASTRIDE + seg * 8, src0 + j * KDIM + seg * 8);
    }
}

#define MMA16816(c0,c1,c2,c3,a0,a1,a2,a3,b0,b1)                                     \
    asm volatile("mma.sync.aligned.m16n8k16.row.col.f32.bf16.bf16.f32 "             \
                 "{%0,%1,%2,%3},{%4,%5,%6,%7},{%8,%9},{%0,%1,%2,%3};"               \
                 : "+f"(c0), "+f"(c1), "+f"(c2), "+f"(c3)                           \
                 : "r"(a0), "r"(a1), "r"(a2), "r"(a3), "r"(b0), "r"(b1))

template <bool APPLY_BN>
__global__ void __launch_bounds__(256, 2)
gemm_kernel(const float* __restrict__ X, const __nv_bfloat16* __restrict__ WP,
            const float* __restrict__ bias,
            const float* __restrict__ bnscale, const float* __restrict__ bnshift,
            float* __restrict__ Y, float* __restrict__ OUT) {
    extern __shared__ char smem[];
    __nv_bfloat16* As = (__nv_bfloat16*)smem;                          // 128 x ASTRIDE
    __nv_bfloat16* Bs = (__nv_bfloat16*)(smem + 128 * ASTRIDE * 2);    // 2 x 64 x ASTRIDE

    const int tid = threadIdx.x;
    const int wid = tid >> 5, lane = tid & 31;
    const int g = lane >> 2, tig = lane & 3;
    const int warpM = wid & 3, warpN = wid >> 2;
    const int mbase = blockIdx.x * 128;

    // --- A tile: 128 rows, 2 input dims per thread iter -> bf16 hi|lo|hi
    for (int it = tid; it < 128 * 32; it += 256) {
        int row = it >> 5;
        int dp = it & 31;
        int grow = mbase + row;
        float2 v = make_float2(0.f, 0.f);
        if (grow < NN) v = *(const float2*)(X + (size_t)grow * 64 + dp * 2);
        if (APPLY_BN) {
            v.x = fmaxf(v.x * bnscale[dp * 2]     + bnshift[dp * 2], 0.f);
            v.y = fmaxf(v.y * bnscale[dp * 2 + 1] + bnshift[dp * 2 + 1], 0.f);
        }
        __nv_bfloat162 hi, lo;
        hi.x = __float2bfloat16(v.x); hi.y = __float2bfloat16(v.y);
        lo.x = __float2bfloat16(v.x - __bfloat162float(hi.x));
        lo.y = __float2bfloat16(v.y - __bfloat162float(hi.y));
        __nv_bfloat162* arow = (__nv_bfloat162*)(As + row * ASTRIDE);
        arow[dp] = hi; arow[32 + dp] = lo; arow[64 + dp] = hi;
    }

    issue_b_chunk(Bs, WP, 0, tid);
    asm volatile("cp.async.commit_group;");

    float c[2][4][4];
#pragma unroll
    for (int a = 0; a < 2; a++)
#pragma unroll
        for (int b = 0; b < 4; b++)
#pragma unroll
            for (int k = 0; k < 4; k++) c[a][b][k] = 0.f;

    const __nv_bfloat16* a0p = As + (warpM * 32 + g) * ASTRIDE;

    for (int nc = 0; nc < 9; nc++) {
        if (nc + 1 < 9) {
            issue_b_chunk(Bs + ((nc + 1) & 1) * 64 * ASTRIDE, WP, nc + 1, tid);
            asm volatile("cp.async.commit_group;");
            asm volatile("cp.async.wait_group 1;");
        } else {
            asm volatile("cp.async.wait_group 0;");
        }
        __syncthreads();

        const __nv_bfloat16* Bb = Bs + (nc & 1) * 64 * ASTRIDE + (warpN * 32 + g) * ASTRIDE;
#pragma unroll
        for (int ks = 0; ks < 12; ks++) {
            const int kc = ks * 16 + 2 * tig;
            unsigned a[2][4], b[4][2];
#pragma unroll
            for (int mt = 0; mt < 2; mt++) {
                const __nv_bfloat16* ap = a0p + mt * 16 * ASTRIDE + kc;
                a[mt][0] = *(const unsigned*)(ap);
                a[mt][2] = *(const unsigned*)(ap + 8);
                a[mt][1] = *(const unsigned*)(ap + 8 * ASTRIDE);
                a[mt][3] = *(const unsigned*)(ap + 8 * ASTRIDE + 8);
            }
#pragma unroll
            for (int nt = 0; nt < 4; nt++) {
                const __nv_bfloat16* bp = Bb + nt * 8 * ASTRIDE + kc;
                b[nt][0] = *(const unsigned*)(bp);
                b[nt][1] = *(const unsigned*)(bp + 8);
            }
#pragma unroll
            for (int mt = 0; mt < 2; mt++)
#pragma unroll
                for (int nt = 0; nt < 4; nt++)
                    MMA16816(c[mt][nt][0], c[mt][nt][1], c[mt][nt][2], c[mt][nt][3],
                             a[mt][0], a[mt][1], a[mt][2], a[mt][3], b[nt][0], b[nt][1]);
        }
        __syncthreads();   // all warps done reading this B buffer before next cp.async reuses it

        // --- epilogue for this 64-col chunk
#pragma unroll
        for (int mt = 0; mt < 2; mt++)
#pragma unroll
            for (int nt = 0; nt < 4; nt++) {
                float* cc = c[mt][nt];
                int row = mbase + warpM * 32 + mt * 16 + g;
                int col = warpN * 32 + nt * 8 + 2 * tig;
                if (nc < 8) {
                    size_t base = (size_t)row * 512 + nc * 64 + col;
                    if (row < NN)     *(float2*)(Y + base)            = make_float2(cc[0], cc[1]);
                    if (row + 8 < NN) *(float2*)(Y + base + 8 * 512)  = make_float2(cc[2], cc[3]);
                } else {
                    float2 bb = *(const float2*)(bias + col);
                    if (row < NN)
                        *(float2*)(OUT + (size_t)row * 64 + col) = make_float2(cc[0] + bb.x, cc[1] + bb.y);
                    if (row + 8 < NN)
                        *(float2*)(OUT + (size_t)(row + 8) * 64 + col) = make_float2(cc[2] + bb.x, cc[3] + bb.y);
                }
                cc[0] = cc[1] = cc[2] = cc[3] = 0.f;
            }
    }
}

// ---------------- edge scatter: OUT[dst] += Y[src,et] * inv[dst,et] ----------------
__global__ void scatter_kernel(const float* __restrict__ Y,
                               const int* __restrict__ SA, const int* __restrict__ SB,
                               const float* __restrict__ INV, float* __restrict__ OUT) {
    int idx = blockIdx.x * 256 + threadIdx.x;   // E*16 threads, float4 each
    int e = idx >> 4;
    if (e >= EE) return;
    int q = idx & 15;
    int sa = SA[e], sb = SB[e];
    float inv = __ldg(INV + sb);
    float4 v = *(const float4*)(Y + (size_t)sa * 64 + q * 4);
    float* dst = OUT + (size_t)(sb >> 3) * 64 + q * 4;
    asm volatile("red.global.add.v4.f32 [%0], {%1,%2,%3,%4};"
                 :: "l"(dst), "f"(v.x * inv), "f"(v.y * inv), "f"(v.z * inv), "f"(v.w * inv)
                 : "memory");
}

// ---------------- batch norm ----------------
__global__ void bn_stats(const float* __restrict__ H, float* __restrict__ acc) {
    int ch = threadIdx.x & 63;
    int ry = threadIdx.x >> 6;  // 0..3
    float s = 0.f, q = 0.f;
    for (int r = blockIdx.x * 4 + ry; r < NN; r += gridDim.x * 4) {
        float v = H[(size_t)r * 64 + ch];
        s += v; q += v * v;
    }
    __shared__ float sh[2][4][64];
    sh[0][ry][ch] = s; sh[1][ry][ch] = q;
    __syncthreads();
    if (ry == 0) {
        s = sh[0][0][ch] + sh[0][1][ch] + sh[0][2][ch] + sh[0][3][ch];
        q = sh[1][0][ch] + sh[1][1][ch] + sh[1][2][ch] + sh[1][3][ch];
        atomicAdd(acc + ch, s);
        atomicAdd(acc + 64 + ch, q);
    }
}

__global__ void bn_final(const float* __restrict__ acc,
                         const float* __restrict__ gamma, const float* __restrict__ beta,
                         float* __restrict__ scale, float* __restrict__ shift) {
    int ch = threadIdx.x;
    if (ch >= 64) return;
    const float invN = 1.0f / (float)NN;
    float mu = acc[ch] * invN;
    float var = acc[64 + ch] * invN - mu * mu;
    float sc = gamma[ch] * rsqrtf(var + 1e-5f);
    scale[ch] = sc;
    shift[ch] = beta[ch] - mu * sc;
}

// ---------------- launcher ----------------
extern "C" void kernel_launch(void* const* d_in, const int* in_sizes, int n_in,
                              void* d_out, int out_size) {
    const float* x      = (const float*)d_in[0];
    const int*   ei     = (const int*)d_in[1];     // int32! (JAX x64 disabled)
    const int*   etype  = (const int*)d_in[2];     // int32!
    const float* w1     = (const float*)d_in[3];
    const float* root1  = (const float*)d_in[4];
    const float* b1     = (const float*)d_in[5];
    const float* gamma1 = (const float*)d_in[6];
    const float* beta1  = (const float*)d_in[7];
    const float* w2     = (const float*)d_in[8];
    const float* root2  = (const float*)d_in[9];
    const float* b2     = (const float*)d_in[10];
    float* out = (float*)d_out;

    float *y, *h, *cnt, *acc, *scale, *shift;
    int *sa, *sb;
    __nv_bfloat16 *wp1, *wp2;
    cudaGetSymbolAddress((void**)&y, g_y);
    cudaGetSymbolAddress((void**)&h, g_h);
    cudaGetSymbolAddress((void**)&cnt, g_cnt);
    cudaGetSymbolAddress((void**)&acc, g_acc);
    cudaGetSymbolAddress((void**)&scale, g_scale);
    cudaGetSymbolAddress((void**)&shift, g_shift);
    cudaGetSymbolAddress((void**)&sa, g_sa);
    cudaGetSymbolAddress((void**)&sb, g_sb);
    cudaGetSymbolAddress((void**)&wp1, g_wp1);
    cudaGetSymbolAddress((void**)&wp2, g_wp2);

    cudaFuncSetAttribute(gemm_kernel<false>, cudaFuncAttributeMaxDynamicSharedMemorySize, SMEM_BYTES);
    cudaFuncSetAttribute(gemm_kernel<true>,  cudaFuncAttributeMaxDynamicSharedMemorySize, SMEM_BYTES);

    const int MT = (NN + 127) / 128;           // 782
    const int SCGRID = (EE * 16) / 256;        // 100000

    zero_kernel<<<(NN * RRR + 255) / 256, 256>>>(cnt, acc);
    prep_edges<<<(EE + 255) / 256, 256>>>(ei, etype, sa, sb, cnt);
    prep_w<<<(576 * KDIM + 255) / 256, 256>>>(w1, root1, wp1);
    prep_w<<<(576 * KDIM + 255) / 256, 256>>>(w2, root2, wp2);
    inv_kernel<<<(NN * RRR + 255) / 256, 256>>>(cnt);

    // layer 1
    gemm_kernel<false><<<MT, 256, SMEM_BYTES>>>(x, wp1, b1, nullptr, nullptr, y, h);
    scatter_kernel<<<SCGRID, 256>>>(y, sa, sb, cnt, h);

    // batch norm stats (applied fused into layer-2 GEMM A-load)
    bn_stats<<<1024, 256>>>(h, acc);
    bn_final<<<1, 64>>>(acc, gamma1, beta1, scale, shift);

    // layer 2
    gemm_kernel<true><<<MT, 256, SMEM_BYTES>>>(h, wp2, b2, scale, shift, y, out);
    scatter_kernel<<<SCGRID, 256>>>(y, sa, sb, cnt, out);
}